// round 2
// baseline (speedup 1.0000x reference)
#include <cuda_runtime.h>
#include <math.h>

// ---------------------------------------------------------------------------
// Static scratch (no allocations allowed)
// ---------------------------------------------------------------------------
__device__ float g_buf1[2048 * 32 * 15 * 15];   // conv1 out  (59 MB)
__device__ float g_buf2[2048 * 64 * 6 * 6];     // conv2 out  (19 MB)
__device__ float g_buf3[2048 * 1024];           // conv3 out / flatten (8.4 MB)
__device__ float g_feats[2048 * 512];           // fc out
__device__ float g_gatesx[2048 * 1024];         // f_t @ w_ih^T + b_ih + b_hh
__device__ float g_hbuf[2][32 * 256];           // LSTM h ping-pong
__device__ unsigned g_count;                    // grid barrier
__device__ unsigned g_gen;

#define SMEM1 ((16384 + 32 * 257) * 4)
#define SMEM2 ((7200 + 64 * 129) * 4)
#define SMEM3 ((9216 + 32 * 577) * 4)
#define SMEML ((16 * 264 + 32 * 264 + 512 + 128) * 4)

// ---------------------------------------------------------------------------
// conv1: in (n,4,64,64)/255 -> relu -> out (n,32,15,15), k=8 s=4
// block = one image, 384 threads; image + weights resident in smem.
// Each active thread computes a 4(oc) x 5(ow) register tile.
// ---------------------------------------------------------------------------
__global__ __launch_bounds__(384, 2)
void conv1_kernel(const float* __restrict__ x, const float* __restrict__ w,
                  const float* __restrict__ bias, float* __restrict__ out)
{
    extern __shared__ float sm[];
    float* img = sm;              // 4*64*64
    float* wts = sm + 16384;      // 32 rows, stride 257

    const int tid = threadIdx.x;
    const int n = blockIdx.x;

    const float4* xin = (const float4*)(x + (size_t)n * 16384);
    const float inv255 = 1.0f / 255.0f;
    for (int i = tid; i < 4096; i += 384) {
        float4 v = xin[i];
        v.x *= inv255; v.y *= inv255; v.z *= inv255; v.w *= inv255;
        *(float4*)(img + i * 4) = v;
    }
    for (int i = tid; i < 8192; i += 384) {
        int oc = i >> 8, r = i & 255;
        wts[oc * 257 + r] = w[i];
    }
    __syncthreads();

    if (tid < 360) {
        const int ocg = tid & 7;            // 8 groups of 4 oc
        const int owg = (tid >> 3) % 3;     // 3 groups of 5 ow
        const int oh  = tid / 24;           // 0..14
        const int oc0 = ocg * 4, ow0 = owg * 5;

        float acc[4][5];
        #pragma unroll
        for (int i = 0; i < 4; i++)
            #pragma unroll
            for (int j = 0; j < 5; j++) acc[i][j] = 0.0f;

        for (int c = 0; c < 4; c++) {
            const float* ib = img + c * 4096 + (oh * 4) * 64 + ow0 * 4;
            const float* wb = wts + c * 64;
            #pragma unroll
            for (int kh = 0; kh < 8; kh++) {
                #pragma unroll
                for (int kw = 0; kw < 8; kw++) {
                    const float x0 = ib[kh * 64 + kw];
                    const float x1 = ib[kh * 64 + 4 + kw];
                    const float x2 = ib[kh * 64 + 8 + kw];
                    const float x3 = ib[kh * 64 + 12 + kw];
                    const float x4 = ib[kh * 64 + 16 + kw];
                    #pragma unroll
                    for (int i = 0; i < 4; i++) {
                        const float wv = wb[(oc0 + i) * 257 + kh * 8 + kw];
                        acc[i][0] += wv * x0;
                        acc[i][1] += wv * x1;
                        acc[i][2] += wv * x2;
                        acc[i][3] += wv * x3;
                        acc[i][4] += wv * x4;
                    }
                }
            }
        }
        float* ob = out + (((size_t)n * 32 + oc0) * 15 + oh) * 15 + ow0;
        #pragma unroll
        for (int i = 0; i < 4; i++) {
            const float bi = bias[oc0 + i];
            #pragma unroll
            for (int j = 0; j < 5; j++) {
                float v = acc[i][j] + bi;
                ob[i * 225 + j] = v > 0.0f ? v : 0.0f;
            }
        }
    }
}

// ---------------------------------------------------------------------------
// conv2: in (n,32,15,15) -> relu -> out (n,64,6,6), k=4 s=2
// block = one image, 192 threads. Input resident; weights chunked by 8 ic.
// Thread tile: 4(oc) x 3(ow).
// ---------------------------------------------------------------------------
__global__ __launch_bounds__(192, 3)
void conv2_kernel(const float* __restrict__ in, const float* __restrict__ w,
                  const float* __restrict__ bias, float* __restrict__ out)
{
    extern __shared__ float sm[];
    float* img = sm;            // 32*15*15 = 7200
    float* wk  = sm + 7200;     // 64 rows, stride 129 (8 ic * 16 per row)

    const int tid = threadIdx.x;
    const int n = blockIdx.x;

    const float4* ip = (const float4*)(in + (size_t)n * 7200);
    for (int i = tid; i < 1800; i += 192) ((float4*)img)[i] = ip[i];

    const int ocg = tid & 15;          // 16 groups of 4 oc
    const int owg = (tid >> 4) & 1;    // 2 groups of 3 ow
    const int oh  = tid >> 5;          // 0..5
    const int oc0 = ocg * 4, ow0 = owg * 3;

    float acc[4][3];
    #pragma unroll
    for (int i = 0; i < 4; i++)
        #pragma unroll
        for (int j = 0; j < 3; j++) acc[i][j] = 0.0f;

    for (int icc = 0; icc < 4; icc++) {
        __syncthreads();
        for (int e = tid; e < 8192; e += 192) {
            int oc = e >> 7, rr = e & 127;
            wk[oc * 129 + rr] = w[oc * 512 + icc * 128 + rr];
        }
        __syncthreads();

        for (int ici = 0; ici < 8; ici++) {
            const float* ib = img + (icc * 8 + ici) * 225 + (oh * 2) * 15 + ow0 * 2;
            const float* wb = wk + ici * 16;
            #pragma unroll
            for (int kh = 0; kh < 4; kh++) {
                #pragma unroll
                for (int kw = 0; kw < 4; kw++) {
                    const float x0 = ib[kh * 15 + kw];
                    const float x1 = ib[kh * 15 + kw + 2];
                    const float x2 = ib[kh * 15 + kw + 4];
                    #pragma unroll
                    for (int i = 0; i < 4; i++) {
                        const float wv = wb[(oc0 + i) * 129 + kh * 4 + kw];
                        acc[i][0] += wv * x0;
                        acc[i][1] += wv * x1;
                        acc[i][2] += wv * x2;
                    }
                }
            }
        }
    }
    float* ob = out + (((size_t)n * 64 + oc0) * 6 + oh) * 6 + ow0;
    #pragma unroll
    for (int i = 0; i < 4; i++) {
        const float bi = bias[oc0 + i];
        #pragma unroll
        for (int j = 0; j < 3; j++) {
            float v = acc[i][j] + bi;
            ob[i * 36 + j] = v > 0.0f ? v : 0.0f;
        }
    }
}

// ---------------------------------------------------------------------------
// conv3: in (n,64,6,6) -> relu -> flatten out (n, 64*16), k=3 s=1
// block = 4 images x 32 oc (half), 128 threads. Thread tile 4(oc) x 4(ow).
// ---------------------------------------------------------------------------
__global__ __launch_bounds__(128, 2)
void conv3_kernel(const float* __restrict__ in, const float* __restrict__ w,
                  const float* __restrict__ bias, float* __restrict__ out)
{
    extern __shared__ float sm[];
    float* img = sm;            // 4 * 2304
    float* wk  = sm + 9216;     // 32 rows, stride 577 (64*9 per row)

    const int tid = threadIdx.x;
    const int nbase = (blockIdx.x >> 1) * 4;
    const int oc0base = (blockIdx.x & 1) * 32;

    const float4* ip = (const float4*)(in + (size_t)nbase * 2304);
    for (int i = tid; i < 2304; i += 128) ((float4*)img)[i] = ip[i];
    for (int e = tid; e < 18432; e += 128) {
        int ocl = e / 576, rr = e - ocl * 576;
        wk[ocl * 577 + rr] = w[(oc0base + ocl) * 576 + rr];
    }
    __syncthreads();

    const int im = tid >> 5;
    const int r  = tid & 31;
    const int ocg = r & 7, oh = r >> 3;
    const int oc0 = ocg * 4;

    float acc[4][4];
    #pragma unroll
    for (int i = 0; i < 4; i++)
        #pragma unroll
        for (int j = 0; j < 4; j++) acc[i][j] = 0.0f;

    const float* ibase = img + im * 2304 + oh * 6;
    for (int ic = 0; ic < 64; ic++) {
        const float* ib = ibase + ic * 36;
        const float* wb = wk + ic * 9;
        #pragma unroll
        for (int kh = 0; kh < 3; kh++) {
            #pragma unroll
            for (int kw = 0; kw < 3; kw++) {
                const float x0 = ib[kh * 6 + kw];
                const float x1 = ib[kh * 6 + kw + 1];
                const float x2 = ib[kh * 6 + kw + 2];
                const float x3 = ib[kh * 6 + kw + 3];
                #pragma unroll
                for (int i = 0; i < 4; i++) {
                    const float wv = wb[(oc0 + i) * 577 + kh * 3 + kw];
                    acc[i][0] += wv * x0;
                    acc[i][1] += wv * x1;
                    acc[i][2] += wv * x2;
                    acc[i][3] += wv * x3;
                }
            }
        }
    }
    const int n = nbase + im;
    #pragma unroll
    for (int i = 0; i < 4; i++) {
        const int oc = oc0base + oc0 + i;
        const float bi = bias[oc];
        #pragma unroll
        for (int j = 0; j < 4; j++) {
            float v = acc[i][j] + bi;
            out[(size_t)n * 1024 + oc * 16 + oh * 4 + j] = v > 0.0f ? v : 0.0f;
        }
    }
}

// ---------------------------------------------------------------------------
// GEMM (NT): C[M,N] = act(A[M,K] * B[N,K]^T + bias1 + bias2)
// 64x64 block tile, 256 threads, 4x4 micro-tile, K chunk 32,
// smem tiles stored k-major-transposed ([kk][m] / [kk][n], stride 68)
// so compute loads are conflict-free LDS.128.
// ---------------------------------------------------------------------------
template <bool RELU>
__global__ __launch_bounds__(256)
void gemm_nt_kernel(const float* __restrict__ A, const float* __restrict__ B,
                    const float* __restrict__ b1, const float* __restrict__ b2,
                    float* __restrict__ C, int K, int N)
{
    __shared__ float As[32 * 68];
    __shared__ float Bs[32 * 68];

    const int tid = threadIdx.x;
    const int m0 = blockIdx.y * 64;
    const int n0 = blockIdx.x * 64;
    const int ty = tid >> 4, tx = tid & 15;

    float acc[4][4];
    #pragma unroll
    for (int i = 0; i < 4; i++)
        #pragma unroll
        for (int j = 0; j < 4; j++) acc[i][j] = 0.0f;

    for (int k0 = 0; k0 < K; k0 += 32) {
        #pragma unroll
        for (int l = 0; l < 2; l++) {
            const int id = tid + l * 256;            // 0..511
            const int row = id >> 3;                 // 0..63
            const int c4 = (id & 7) * 4;             // 0..28
            float4 av = *(const float4*)(A + (size_t)(m0 + row) * K + k0 + c4);
            float4 bv = *(const float4*)(B + (size_t)(n0 + row) * K + k0 + c4);
            As[(c4 + 0) * 68 + row] = av.x;
            As[(c4 + 1) * 68 + row] = av.y;
            As[(c4 + 2) * 68 + row] = av.z;
            As[(c4 + 3) * 68 + row] = av.w;
            Bs[(c4 + 0) * 68 + row] = bv.x;
            Bs[(c4 + 1) * 68 + row] = bv.y;
            Bs[(c4 + 2) * 68 + row] = bv.z;
            Bs[(c4 + 3) * 68 + row] = bv.w;
        }
        __syncthreads();
        #pragma unroll
        for (int kk = 0; kk < 32; kk++) {
            const float4 av = *(const float4*)(As + kk * 68 + ty * 4);
            const float4 bv = *(const float4*)(Bs + kk * 68 + tx * 4);
            acc[0][0] += av.x * bv.x; acc[0][1] += av.x * bv.y;
            acc[0][2] += av.x * bv.z; acc[0][3] += av.x * bv.w;
            acc[1][0] += av.y * bv.x; acc[1][1] += av.y * bv.y;
            acc[1][2] += av.y * bv.z; acc[1][3] += av.y * bv.w;
            acc[2][0] += av.z * bv.x; acc[2][1] += av.z * bv.y;
            acc[2][2] += av.z * bv.z; acc[2][3] += av.z * bv.w;
            acc[3][0] += av.w * bv.x; acc[3][1] += av.w * bv.y;
            acc[3][2] += av.w * bv.z; acc[3][3] += av.w * bv.w;
        }
        __syncthreads();
    }

    #pragma unroll
    for (int j = 0; j < 4; j++) {
        const int col = n0 + tx * 4 + j;
        float bb = b1[col] + (b2 ? b2[col] : 0.0f);
        #pragma unroll
        for (int i = 0; i < 4; i++) {
            float v = acc[i][j] + bb;
            if (RELU) v = v > 0.0f ? v : 0.0f;
            C[(size_t)(m0 + ty * 4 + i) * N + col] = v;
        }
    }
}

// ---------------------------------------------------------------------------
// LSTM: 64 blocks x 256 threads. Block b owns hidden cols [4b, 4b+4).
// w_hh slice (16 rows x 256) resident in smem for all 64 steps.
// c state block-local; h exchanged via L2 ping-pong + software grid barrier.
// ---------------------------------------------------------------------------
__global__ __launch_bounds__(256, 1)
void lstm_kernel(const float* __restrict__ gx, const float* __restrict__ whh,
                 const int* __restrict__ done,
                 const float* __restrict__ h0, const float* __restrict__ c0,
                 float* __restrict__ out)
{
    extern __shared__ float sm[];
    float* ws     = sm;                    // 16 rows, stride 264
    float* h_s    = sm + 16 * 264;         // 32 rows, stride 264
    float* gate_s = h_s + 32 * 264;        // 512
    float* c_s    = gate_s + 512;          // 128

    const int tid = threadIdx.x;
    const int j0 = blockIdx.x * 4;

    // w_hh slice: smem row r = g*4 + jj <- global row g*256 + j0 + jj
    #pragma unroll
    for (int l = 0; l < 4; l++) {
        const int id = tid + l * 256;      // 0..1023
        const int r = id >> 6;
        const int c4 = (id & 63) * 4;
        const int g = r >> 2, jj = r & 3;
        *(float4*)(ws + r * 264 + c4) =
            *(const float4*)(whh + (size_t)(g * 256 + j0 + jj) * 256 + c4);
    }
    if (tid < 128) {
        const int b = tid >> 2, jj = tid & 3;
        c_s[tid] = c0[b * 256 + j0 + jj];
    }
    unsigned bar_gen = 0;
    if (tid == 0) bar_gen = *((volatile unsigned*)&g_gen);
    __syncthreads();

    const int u = tid & 7;
    const int b = tid >> 3;
    const int jj = u & 3, gh = u >> 2;
    const float* w0 = ws + ((2 * gh) * 4 + jj) * 264;
    const float* w1 = ws + ((2 * gh + 1) * 4 + jj) * 264;
    const float* hb = h_s + b * 264;

    for (int t = 0; t < 64; t++) {
        // stage masked h into smem
        const float* hsrc = (t == 0) ? h0 : g_hbuf[(t - 1) & 1];
        const int* dn = done + t * 32;
        #pragma unroll
        for (int l = 0; l < 8; l++) {
            const int f = tid + l * 256;       // 0..2047
            const int bb = f >> 6;
            const int kc = (f & 63) * 4;
            const float m = 1.0f - (float)dn[bb];
            float4 v = *(const float4*)(hsrc + bb * 256 + kc);
            v.x *= m; v.y *= m; v.z *= m; v.w *= m;
            *(float4*)(h_s + bb * 264 + kc) = v;
        }
        __syncthreads();

        // two gate dot products of length 256
        float s00 = 0, s01 = 0, s02 = 0, s03 = 0;
        float s10 = 0, s11 = 0, s12 = 0, s13 = 0;
        #pragma unroll 8
        for (int k = 0; k < 256; k += 4) {
            const float4 h4 = *(const float4*)(hb + k);
            const float4 wa = *(const float4*)(w0 + k);
            const float4 wb4 = *(const float4*)(w1 + k);
            s00 += h4.x * wa.x;  s01 += h4.y * wa.y;
            s02 += h4.z * wa.z;  s03 += h4.w * wa.w;
            s10 += h4.x * wb4.x; s11 += h4.y * wb4.y;
            s12 += h4.z * wb4.z; s13 += h4.w * wb4.w;
        }
        const int row = t * 32 + b;
        const float g0v = ((s00 + s01) + (s02 + s03)) +
                          gx[(size_t)row * 1024 + (2 * gh) * 256 + j0 + jj];
        const float g1v = ((s10 + s11) + (s12 + s13)) +
                          gx[(size_t)row * 1024 + (2 * gh + 1) * 256 + j0 + jj];
        gate_s[(b * 4 + jj) * 4 + 2 * gh] = g0v;
        gate_s[(b * 4 + jj) * 4 + 2 * gh + 1] = g1v;
        __syncthreads();

        // state update (one thread per (b, jj))
        if (tid < 128) {
            const int bb = tid >> 2, j2 = tid & 3;
            const float* gp = gate_s + tid * 4;
            const float gi = gp[0], gf = gp[1], gg = gp[2], go = gp[3];
            const float m = 1.0f - (float)dn[bb];
            const float cold = c_s[tid] * m;
            const float si = 1.0f / (1.0f + __expf(-gi));
            const float sf = 1.0f / (1.0f + __expf(-gf));
            const float so = 1.0f / (1.0f + __expf(-go));
            const float cn = sf * cold + si * tanhf(gg);
            const float h = so * tanhf(cn);
            c_s[tid] = cn;
            const int j = j0 + j2;
            g_hbuf[t & 1][bb * 256 + j] = h;
            out[(size_t)(t * 32 + bb) * 256 + j] = h;
        }
        __threadfence();
        __syncthreads();

        if (t < 63) {   // grid barrier
            if (tid == 0) {
                const unsigned prev = atomicAdd(&g_count, 1);
                if (prev == gridDim.x - 1) {
                    g_count = 0;
                    __threadfence();
                    atomicAdd(&g_gen, 1);
                } else {
                    while (*((volatile unsigned*)&g_gen) == bar_gen) { }
                }
                bar_gen++;
                __threadfence();
            }
            __syncthreads();
        }
    }
}

// ---------------------------------------------------------------------------
extern "C" void kernel_launch(void* const* d_in, const int* in_sizes, int n_in,
                              void* d_out, int out_size)
{
    const float* x    = (const float*)d_in[0];
    const int*   done = (const int*)d_in[1];
    const float* w1   = (const float*)d_in[2];
    const float* b1   = (const float*)d_in[3];
    const float* w2   = (const float*)d_in[4];
    const float* b2   = (const float*)d_in[5];
    const float* w3   = (const float*)d_in[6];
    const float* b3   = (const float*)d_in[7];
    const float* fcw  = (const float*)d_in[8];
    const float* fcb  = (const float*)d_in[9];
    const float* wih  = (const float*)d_in[10];
    const float* whh  = (const float*)d_in[11];
    const float* bih  = (const float*)d_in[12];
    const float* bhh  = (const float*)d_in[13];
    const float* h0   = (const float*)d_in[14];
    const float* c0   = (const float*)d_in[15];
    float* out = (float*)d_out;

    float *buf1, *buf2, *buf3, *feats, *gatesx;
    cudaGetSymbolAddress((void**)&buf1,   g_buf1);
    cudaGetSymbolAddress((void**)&buf2,   g_buf2);
    cudaGetSymbolAddress((void**)&buf3,   g_buf3);
    cudaGetSymbolAddress((void**)&feats,  g_feats);
    cudaGetSymbolAddress((void**)&gatesx, g_gatesx);

    cudaFuncSetAttribute(conv1_kernel, cudaFuncAttributeMaxDynamicSharedMemorySize, SMEM1);
    cudaFuncSetAttribute(conv2_kernel, cudaFuncAttributeMaxDynamicSharedMemorySize, SMEM2);
    cudaFuncSetAttribute(conv3_kernel, cudaFuncAttributeMaxDynamicSharedMemorySize, SMEM3);
    cudaFuncSetAttribute(lstm_kernel,  cudaFuncAttributeMaxDynamicSharedMemorySize, SMEML);

    conv1_kernel<<<2048, 384, SMEM1>>>(x, w1, b1, buf1);
    conv2_kernel<<<2048, 192, SMEM2>>>(buf1, w2, b2, buf2);
    conv3_kernel<<<1024, 128, SMEM3>>>(buf2, w3, b3, buf3);
    gemm_nt_kernel<true><<<dim3(8, 32), 256>>>(buf3, fcw, fcb, nullptr, feats, 1024, 512);
    gemm_nt_kernel<false><<<dim3(16, 32), 256>>>(feats, wih, bih, bhh, gatesx, 512, 1024);
    lstm_kernel<<<64, 256, SMEML>>>(gatesx, whh, done, h0, c0, out);
}